// round 8
// baseline (speedup 1.0000x reference)
#include <cuda_runtime.h>

#define NN 50000
#define NE 800000
#define IND 128
#define HD 64
#define OD 64
#define NG 512

// ---------------- scratch (__device__ globals: no allocs allowed) ----------
__device__ int   g_is64;
__device__ int   g_degcnt[NN];
__device__ int   g_cursor[NN];
__device__ int   g_offsets[NN + 1];
__device__ float g_dinv[NN];
__device__ int2  g_ed32[NE];      // packed (src,dst) int32, sequential
__device__ int2  g_edge[NE];      // (src, norm-bits) CSR by dst
__device__ float g_t1[NN * HD];
__device__ float g_agg1[NN * HD];
__device__ float g_t2[NN * OD];
__device__ float g_agg2[NN * OD];

// ---------------- helpers --------------------------------------------------
typedef unsigned long long ull;

__device__ __forceinline__ long long ld_idx(const void* p, long long i) {
    if (g_is64) return ((const long long*)p)[i];
    return (long long)((const int*)p)[i];
}

__device__ __forceinline__ ull pack2(float x, float y) {
    ull r; asm("mov.b64 %0, {%1, %2};" : "=l"(r) : "f"(x), "f"(y)); return r;
}
__device__ __forceinline__ float2 unpack2(ull v) {
    float2 f; asm("mov.b64 {%0, %1}, %2;" : "=f"(f.x), "=f"(f.y) : "l"(v)); return f;
}
// d = a * b + d  (two independent fp32 FMAs, bit-identical to scalar fmaf)
__device__ __forceinline__ void ffma2(ull& d, ull a, ull b) {
    asm("fma.rn.f32x2 %0, %1, %2, %0;" : "+l"(d) : "l"(a), "l"(b));
}

// ---------------- init: zero counters + int64/int32 detect -----------------
__global__ void init_kernel(const void* __restrict__ ei) {
    int i = blockIdx.x * blockDim.x + threadIdx.x;
    if (i < NN) { g_degcnt[i] = 0; g_cursor[i] = 0; }
    if (i == 0) {
        const long long* p = (const long long*)ei;
        int ok = 1;
        for (int j = 0; j < 64; j++) {
            long long v = p[j];
            if (v < 0 || v >= NN) { ok = 0; break; }
        }
        g_is64 = ok;  // int32 data read as int64 fails the range check w.h.p.
    }
}

// count + decode int64 -> packed int32 pairs (fill re-reads the cheap form)
__global__ void count_kernel(const void* __restrict__ ei) {
    int e = blockIdx.x * blockDim.x + threadIdx.x;
    if (e < NE) {
        int s = (int)ld_idx(ei, e);
        int d = (int)ld_idx(ei, (long long)NE + e);
        g_ed32[e] = make_int2(s, d);
        atomicAdd(&g_degcnt[d], 1);
    }
}

// single-block exclusive scan of degcnt (49 elems/thread), dinv fused
__global__ void __launch_bounds__(1024) scan_kernel() {
    __shared__ int warp_sums[32];
    const int t = threadIdx.x;
    const int CH = 49;                 // 1024*49 = 50176 >= NN
    const int base = t * CH;
    int sum = 0;
#pragma unroll 7
    for (int i = 0; i < CH; i++) {
        int idx = base + i;
        if (idx < NN) sum += g_degcnt[idx];
    }
    int lane = t & 31, warp = t >> 5;
    int v = sum;
#pragma unroll
    for (int o = 1; o < 32; o <<= 1) {
        int u = __shfl_up_sync(~0u, v, o);
        if (lane >= o) v += u;
    }
    if (lane == 31) warp_sums[warp] = v;
    __syncthreads();
    if (warp == 0) {
        int w = warp_sums[lane];
#pragma unroll
        for (int o = 1; o < 32; o <<= 1) {
            int u = __shfl_up_sync(~0u, w, o);
            if (lane >= o) w += u;
        }
        warp_sums[lane] = w;
    }
    __syncthreads();
    int run = v - sum + (warp ? warp_sums[warp - 1] : 0);  // exclusive prefix
#pragma unroll 7
    for (int i = 0; i < CH; i++) {
        int idx = base + i;
        if (idx < NN) {
            int d = g_degcnt[idx];
            g_offsets[idx] = run;
            g_dinv[idx] = rsqrtf(fmaxf((float)d, 1.0f));
            run += d;
        }
    }
    if (t == 0) g_offsets[NN] = NE;
}

__global__ void fill_kernel() {
    int e = blockIdx.x * blockDim.x + threadIdx.x;
    if (e < NE) {
        int2 sd = g_ed32[e];
        int pos = g_offsets[sd.y] + atomicAdd(&g_cursor[sd.y], 1);
        g_edge[pos] = make_int2(sd.x, __float_as_int(g_dinv[sd.x] * g_dinv[sd.y]));
    }
}

// ---------------- dense GEMM: 64 rows x 64 cols per block, FFMA2 mainloop --
template <int K, bool RELU>
__device__ __forceinline__ void gemm_body(const float* __restrict__ A,
                                          const float* __restrict__ W,
                                          const float* __restrict__ bias,
                                          float* __restrict__ out) {
    extern __shared__ float smem[];
    float* Ws = smem;           // K * 64
    float* As = smem + K * 64;  // K * 64
    const int t = threadIdx.x;
    const int rowbase = blockIdx.x * 64;
    constexpr int NQ = K / 4;

    {
        const float4* W4 = (const float4*)W;
        float4* Ws4 = (float4*)Ws;
        for (int i = t; i < K * 16; i += 256) Ws4[i] = W4[i];
    }
    for (int i = t; i < 64 * NQ; i += 256) {
        int r = i / NQ, kq = i - r * NQ;
        int row = rowbase + r;
        float4 v = make_float4(0.f, 0.f, 0.f, 0.f);
        if (row < NN) {
            v = ((const float4*)A)[row * NQ + kq];
            if (RELU) {
                v.x = fmaxf(v.x, 0.f); v.y = fmaxf(v.y, 0.f);
                v.z = fmaxf(v.z, 0.f); v.w = fmaxf(v.w, 0.f);
            }
        }
        int k0 = kq * 4;
        int rs = r ^ (k0 & 28);
        As[(k0 + 0) * 64 + rs] = v.x;
        As[(k0 + 1) * 64 + rs] = v.y;
        As[(k0 + 2) * 64 + rs] = v.z;
        As[(k0 + 3) * 64 + rs] = v.w;
    }
    __syncthreads();

    const int tx = t & 15, ty = t >> 4;
    const int c0 = tx * 4;
    const int r0 = ty * 4;

    ull ac[4][2];
#pragma unroll
    for (int j = 0; j < 4; j++) { ac[j][0] = 0ULL; ac[j][1] = 0ULL; }

#pragma unroll 8
    for (int k = 0; k < K; k++) {
        const float* wrow = Ws + k * 64 + c0;
        ull b01 = *(const ull*)(wrow);
        ull b23 = *(const ull*)(wrow + 2);
        float4 xv = *(const float4*)(As + k * 64 + (r0 ^ (k & 28)));
        ull x0 = pack2(xv.x, xv.x);
        ull x1 = pack2(xv.y, xv.y);
        ull x2 = pack2(xv.z, xv.z);
        ull x3 = pack2(xv.w, xv.w);
        ffma2(ac[0][0], x0, b01); ffma2(ac[0][1], x0, b23);
        ffma2(ac[1][0], x1, b01); ffma2(ac[1][1], x1, b23);
        ffma2(ac[2][0], x2, b01); ffma2(ac[2][1], x2, b23);
        ffma2(ac[3][0], x3, b01); ffma2(ac[3][1], x3, b23);
    }

    float4 bb = *(const float4*)(bias + c0);
#pragma unroll
    for (int j = 0; j < 4; j++) {
        int row = rowbase + r0 + j;
        if (row < NN) {
            float2 p01 = unpack2(ac[j][0]);
            float2 p23 = unpack2(ac[j][1]);
            *(float4*)&out[row * 64 + c0] =
                make_float4(p01.x + bb.x, p01.y + bb.y, p23.x + bb.z, p23.y + bb.w);
        }
    }
}

__global__ void __launch_bounds__(256) gemm1_kernel(const float* __restrict__ x,
                                                    const float* __restrict__ W,
                                                    const float* __restrict__ b) {
    gemm_body<IND, false>(x, W, b, g_t1);
}
__global__ void __launch_bounds__(256) gemm2_kernel(const float* __restrict__ W,
                                                    const float* __restrict__ b) {
    gemm_body<HD, true>(g_agg1, W, b, g_t2);
}

// ---------------- CSR gather aggregation: 16 lanes (float4) per node -------
__device__ __forceinline__ void gather_body(const float* __restrict__ feat,
                                            float* __restrict__ out) {
    int tid = blockIdx.x * blockDim.x + threadIdx.x;
    int node = tid >> 4;
    int lane = tid & 15;
    if (node >= NN) return;
    int beg = g_offsets[node], end = g_offsets[node + 1];
    const float4* f4 = (const float4*)feat;
    float4 a0 = make_float4(0.f, 0.f, 0.f, 0.f);
    float4 a1 = make_float4(0.f, 0.f, 0.f, 0.f);
    int e = beg;
    for (; e + 2 <= end; e += 2) {
        int2 ed0 = g_edge[e];
        int2 ed1 = g_edge[e + 1];
        float4 v0 = f4[ed0.x * 16 + lane];
        float4 v1 = f4[ed1.x * 16 + lane];
        float w0 = __int_as_float(ed0.y);
        float w1 = __int_as_float(ed1.y);
        a0.x = fmaf(v0.x, w0, a0.x); a0.y = fmaf(v0.y, w0, a0.y);
        a0.z = fmaf(v0.z, w0, a0.z); a0.w = fmaf(v0.w, w0, a0.w);
        a1.x = fmaf(v1.x, w1, a1.x); a1.y = fmaf(v1.y, w1, a1.y);
        a1.z = fmaf(v1.z, w1, a1.z); a1.w = fmaf(v1.w, w1, a1.w);
    }
    if (e < end) {
        int2 ed = g_edge[e];
        float4 v = f4[ed.x * 16 + lane];
        float w = __int_as_float(ed.y);
        a0.x = fmaf(v.x, w, a0.x); a0.y = fmaf(v.y, w, a0.y);
        a0.z = fmaf(v.z, w, a0.z); a0.w = fmaf(v.w, w, a0.w);
    }
    ((float4*)out)[node * 16 + lane] =
        make_float4(a0.x + a1.x, a0.y + a1.y, a0.z + a1.z, a0.w + a1.w);
}

__global__ void __launch_bounds__(256) gather1_kernel() { gather_body(g_t1, g_agg1); }
__global__ void __launch_bounds__(256) gather2_kernel() { gather_body(g_t2, g_agg2); }

// ---------------- segment-mean pooling over sorted batch (relu fused) ------
__global__ void pool_kernel(const void* __restrict__ batch, float* __restrict__ out) {
    __shared__ int sb[2];
    int g = blockIdx.x;
    if (threadIdx.x < 2) {
        long long key = (long long)g + threadIdx.x;
        int lo = 0, hi = NN;
        while (lo < hi) {
            int m = (lo + hi) >> 1;
            if (ld_idx(batch, m) < key) lo = m + 1; else hi = m;
        }
        sb[threadIdx.x] = lo;
    }
    __syncthreads();
    int beg = sb[0], end = sb[1];
    int c = threadIdx.x;  // 64 cols
    float sum = 0.f;
    for (int r = beg; r < end; r++) sum += fmaxf(g_agg2[r * 64 + c], 0.f);
    float cnt = (float)(end - beg);
    out[g * 64 + c] = sum / fmaxf(cnt, 1.0f);
}

// ---------------- fork/join resources (static init: before mem checkpoints)
static cudaStream_t g_sB = []() {
    cudaStream_t s = nullptr;
    cudaStreamCreateWithFlags(&s, cudaStreamNonBlocking);
    return s;
}();
static cudaEvent_t g_eFork = []() {
    cudaEvent_t e = nullptr;
    cudaEventCreateWithFlags(&e, cudaEventDisableTiming);
    return e;
}();
static cudaEvent_t g_eJoin = []() {
    cudaEvent_t e = nullptr;
    cudaEventCreateWithFlags(&e, cudaEventDisableTiming);
    return e;
}();

// ---------------- driver ---------------------------------------------------
extern "C" void kernel_launch(void* const* d_in, const int* in_sizes, int n_in,
                              void* d_out, int out_size) {
    const float* x  = (const float*)d_in[0];
    const void*  ei = d_in[1];
    const void*  bt = d_in[2];
    const float* W1 = (const float*)d_in[3];
    const float* b1 = (const float*)d_in[4];
    const float* W2 = (const float*)d_in[5];
    const float* b2 = (const float*)d_in[6];
    float* out = (float*)d_out;

    const int SMEM1 = 2 * IND * 64 * (int)sizeof(float);  // 65536
    const int SMEM2 = 2 * HD * 64 * (int)sizeof(float);   // 32768
    cudaFuncSetAttribute(gemm1_kernel, cudaFuncAttributeMaxDynamicSharedMemorySize, SMEM1);
    cudaFuncSetAttribute(gemm2_kernel, cudaFuncAttributeMaxDynamicSharedMemorySize, SMEM2);

    bool fork = (g_sB != nullptr) && (g_eFork != nullptr) && (g_eJoin != nullptr);

    if (fork) {
        // side branch: gemm1 (independent of the CSR build) runs in parallel
        cudaEventRecord(g_eFork, 0);
        cudaStreamWaitEvent(g_sB, g_eFork, 0);
        gemm1_kernel<<<(NN + 63) / 64, 256, SMEM1, g_sB>>>(x, W1, b1);
        cudaEventRecord(g_eJoin, g_sB);
    }

    // main branch: CSR build
    init_kernel<<<(NN + 255) / 256, 256>>>(ei);
    count_kernel<<<(NE + 255) / 256, 256>>>(ei);
    scan_kernel<<<1, 1024>>>();
    fill_kernel<<<(NE + 255) / 256, 256>>>();

    if (fork) {
        cudaStreamWaitEvent(0, g_eJoin, 0);
    } else {
        gemm1_kernel<<<(NN + 63) / 64, 256, SMEM1>>>(x, W1, b1);
    }

    gather1_kernel<<<(NN * 16 + 255) / 256, 256>>>();
    gemm2_kernel<<<(NN + 63) / 64, 256, SMEM2>>>(W2, b2);
    gather2_kernel<<<(NN * 16 + 255) / 256, 256>>>();
    pool_kernel<<<NG, 64>>>(bt, out);
}

// round 9
// speedup vs baseline: 1.2361x; 1.2361x over previous
#include <cuda_runtime.h>

#define NN 50000
#define NE 800000
#define IND 128
#define HD 64
#define OD 64
#define NG 512

static const int SCAN_BLK = (NN + 1023) / 1024;  // 49

// ---------------- scratch (__device__ globals: no allocs allowed) ----------
__device__ int   g_is64;
__device__ int   g_degcnt[NN];
__device__ int   g_cursor[NN];
__device__ int   g_offsets[NN + 1];   // intra-block exclusive prefix; [NN]=NE absolute
__device__ int   g_blocksums[64];
__device__ int   g_blockbase[64];     // exclusive prefix of block sums
__device__ float g_dinv[NN];
__device__ int2  g_ed32[NE];          // packed (src,dst) int32, sequential
__device__ int2  g_edge[NE];          // (src, norm-bits) CSR by dst
__device__ float g_t1[NN * HD];
__device__ float g_agg1[NN * HD];
__device__ float g_t2[NN * OD];
__device__ float g_agg2[NN * OD];

// ---------------- helpers --------------------------------------------------
typedef unsigned long long ull;

__device__ __forceinline__ long long ld_idx(const void* p, long long i) {
    if (g_is64) return ((const long long*)p)[i];
    return (long long)((const int*)p)[i];
}

// final CSR offset (folds the per-block scan base in at read time)
__device__ __forceinline__ int off(int i) {
    int v = g_offsets[i];
    if (i < NN) v += g_blockbase[i >> 10];
    return v;
}

__device__ __forceinline__ ull pack2(float x, float y) {
    ull r; asm("mov.b64 %0, {%1, %2};" : "=l"(r) : "f"(x), "f"(y)); return r;
}
__device__ __forceinline__ float2 unpack2(ull v) {
    float2 f; asm("mov.b64 {%0, %1}, %2;" : "=f"(f.x), "=f"(f.y) : "l"(v)); return f;
}
// d = a * b + d  (two independent fp32 FMAs, bit-identical to scalar fmaf)
__device__ __forceinline__ void ffma2(ull& d, ull a, ull b) {
    asm("fma.rn.f32x2 %0, %1, %2, %0;" : "+l"(d) : "l"(a), "l"(b));
}

// ---------------- init: zero counters + int64/int32 detect -----------------
__global__ void init_kernel(const void* __restrict__ ei) {
    int i = blockIdx.x * blockDim.x + threadIdx.x;
    if (i < NN) { g_degcnt[i] = 0; g_cursor[i] = 0; }
    if (i == 0) {
        const long long* p = (const long long*)ei;
        int ok = 1;
        for (int j = 0; j < 64; j++) {
            long long v = p[j];
            if (v < 0 || v >= NN) { ok = 0; break; }
        }
        g_is64 = ok;  // int32 data read as int64 fails the range check w.h.p.
    }
}

// count + decode int64 -> packed int32 pairs (fill re-reads the cheap form)
__global__ void count_kernel(const void* __restrict__ ei) {
    int e = blockIdx.x * blockDim.x + threadIdx.x;
    if (e < NE) {
        int s = (int)ld_idx(ei, e);
        int d = (int)ld_idx(ei, (long long)NE + e);
        g_ed32[e] = make_int2(s, d);
        atomicAdd(&g_degcnt[d], 1);
    }
}

// per-block (1024) exclusive scan of degcnt; also emits dinv + block sums
__global__ void __launch_bounds__(1024) scanA_kernel() {
    __shared__ int s[1024];
    int t = threadIdx.x;
    int idx = blockIdx.x * 1024 + t;
    int v = (idx < NN) ? g_degcnt[idx] : 0;
    s[t] = v;
    __syncthreads();
    for (int o = 1; o < 1024; o <<= 1) {
        int tmp = (t >= o) ? s[t - o] : 0;
        __syncthreads();
        if (t >= o) s[t] += tmp;
        __syncthreads();
    }
    if (idx < NN) {
        g_offsets[idx] = s[t] - v;  // exclusive within block
        g_dinv[idx] = rsqrtf(fmaxf((float)v, 1.0f));
    }
    if (t == 1023) g_blocksums[blockIdx.x] = s[1023];
}

// tiny scan of the 49 block sums
__global__ void scanB_kernel() {
    __shared__ int s[64];
    int t = threadIdx.x;
    int v = (t < SCAN_BLK) ? g_blocksums[t] : 0;
    s[t] = v;
    __syncthreads();
    for (int o = 1; o < 64; o <<= 1) {
        int tmp = (t >= o) ? s[t - o] : 0;
        __syncthreads();
        if (t >= o) s[t] += tmp;
        __syncthreads();
    }
    g_blockbase[t] = s[t] - v;  // exclusive
    if (t == 0) g_offsets[NN] = NE;
}

__global__ void fill_kernel() {
    int e = blockIdx.x * blockDim.x + threadIdx.x;
    if (e < NE) {
        int2 sd = g_ed32[e];
        int pos = off(sd.y) + atomicAdd(&g_cursor[sd.y], 1);
        g_edge[pos] = make_int2(sd.x, __float_as_int(g_dinv[sd.x] * g_dinv[sd.y]));
    }
}

// ---------------- dense GEMM: 64 rows x 64 cols per block, FFMA2 mainloop --
template <int K, bool RELU>
__device__ __forceinline__ void gemm_body(const float* __restrict__ A,
                                          const float* __restrict__ W,
                                          const float* __restrict__ bias,
                                          float* __restrict__ out) {
    extern __shared__ float smem[];
    float* Ws = smem;           // K * 64
    float* As = smem + K * 64;  // K * 64
    const int t = threadIdx.x;
    const int rowbase = blockIdx.x * 64;
    constexpr int NQ = K / 4;

    {
        const float4* W4 = (const float4*)W;
        float4* Ws4 = (float4*)Ws;
        for (int i = t; i < K * 16; i += 256) Ws4[i] = W4[i];
    }
    for (int i = t; i < 64 * NQ; i += 256) {
        int r = i / NQ, kq = i - r * NQ;
        int row = rowbase + r;
        float4 v = make_float4(0.f, 0.f, 0.f, 0.f);
        if (row < NN) {
            v = ((const float4*)A)[row * NQ + kq];
            if (RELU) {
                v.x = fmaxf(v.x, 0.f); v.y = fmaxf(v.y, 0.f);
                v.z = fmaxf(v.z, 0.f); v.w = fmaxf(v.w, 0.f);
            }
        }
        int k0 = kq * 4;
        int rs = r ^ (k0 & 28);
        As[(k0 + 0) * 64 + rs] = v.x;
        As[(k0 + 1) * 64 + rs] = v.y;
        As[(k0 + 2) * 64 + rs] = v.z;
        As[(k0 + 3) * 64 + rs] = v.w;
    }
    __syncthreads();

    const int tx = t & 15, ty = t >> 4;
    const int c0 = tx * 4;
    const int r0 = ty * 4;

    ull ac[4][2];
#pragma unroll
    for (int j = 0; j < 4; j++) { ac[j][0] = 0ULL; ac[j][1] = 0ULL; }

#pragma unroll 8
    for (int k = 0; k < K; k++) {
        const float* wrow = Ws + k * 64 + c0;
        ull b01 = *(const ull*)(wrow);
        ull b23 = *(const ull*)(wrow + 2);
        float4 xv = *(const float4*)(As + k * 64 + (r0 ^ (k & 28)));
        ull x0 = pack2(xv.x, xv.x);
        ull x1 = pack2(xv.y, xv.y);
        ull x2 = pack2(xv.z, xv.z);
        ull x3 = pack2(xv.w, xv.w);
        ffma2(ac[0][0], x0, b01); ffma2(ac[0][1], x0, b23);
        ffma2(ac[1][0], x1, b01); ffma2(ac[1][1], x1, b23);
        ffma2(ac[2][0], x2, b01); ffma2(ac[2][1], x2, b23);
        ffma2(ac[3][0], x3, b01); ffma2(ac[3][1], x3, b23);
    }

    float4 bb = *(const float4*)(bias + c0);
#pragma unroll
    for (int j = 0; j < 4; j++) {
        int row = rowbase + r0 + j;
        if (row < NN) {
            float2 p01 = unpack2(ac[j][0]);
            float2 p23 = unpack2(ac[j][1]);
            *(float4*)&out[row * 64 + c0] =
                make_float4(p01.x + bb.x, p01.y + bb.y, p23.x + bb.z, p23.y + bb.w);
        }
    }
}

__global__ void __launch_bounds__(256) gemm1_kernel(const float* __restrict__ x,
                                                    const float* __restrict__ W,
                                                    const float* __restrict__ b) {
    gemm_body<IND, false>(x, W, b, g_t1);
}
__global__ void __launch_bounds__(256) gemm2_kernel(const float* __restrict__ W,
                                                    const float* __restrict__ b) {
    gemm_body<HD, true>(g_agg1, W, b, g_t2);
}

// ---------------- CSR gather aggregation: 16 lanes (float4) per node -------
__device__ __forceinline__ void gather_body(const float* __restrict__ feat,
                                            float* __restrict__ out) {
    int tid = blockIdx.x * blockDim.x + threadIdx.x;
    int node = tid >> 4;
    int lane = tid & 15;
    if (node >= NN) return;
    int beg = off(node), end = off(node + 1);
    const float4* f4 = (const float4*)feat;
    float4 a0 = make_float4(0.f, 0.f, 0.f, 0.f);
    float4 a1 = make_float4(0.f, 0.f, 0.f, 0.f);
    int e = beg;
    for (; e + 2 <= end; e += 2) {
        int2 ed0 = g_edge[e];
        int2 ed1 = g_edge[e + 1];
        float4 v0 = f4[ed0.x * 16 + lane];
        float4 v1 = f4[ed1.x * 16 + lane];
        float w0 = __int_as_float(ed0.y);
        float w1 = __int_as_float(ed1.y);
        a0.x = fmaf(v0.x, w0, a0.x); a0.y = fmaf(v0.y, w0, a0.y);
        a0.z = fmaf(v0.z, w0, a0.z); a0.w = fmaf(v0.w, w0, a0.w);
        a1.x = fmaf(v1.x, w1, a1.x); a1.y = fmaf(v1.y, w1, a1.y);
        a1.z = fmaf(v1.z, w1, a1.z); a1.w = fmaf(v1.w, w1, a1.w);
    }
    if (e < end) {
        int2 ed = g_edge[e];
        float4 v = f4[ed.x * 16 + lane];
        float w = __int_as_float(ed.y);
        a0.x = fmaf(v.x, w, a0.x); a0.y = fmaf(v.y, w, a0.y);
        a0.z = fmaf(v.z, w, a0.z); a0.w = fmaf(v.w, w, a0.w);
    }
    ((float4*)out)[node * 16 + lane] =
        make_float4(a0.x + a1.x, a0.y + a1.y, a0.z + a1.z, a0.w + a1.w);
}

__global__ void __launch_bounds__(256) gather1_kernel() { gather_body(g_t1, g_agg1); }
__global__ void __launch_bounds__(256) gather2_kernel() { gather_body(g_t2, g_agg2); }

// ---------------- segment-mean pooling over sorted batch (relu fused) ------
__global__ void pool_kernel(const void* __restrict__ batch, float* __restrict__ out) {
    __shared__ int sb[2];
    int g = blockIdx.x;
    if (threadIdx.x < 2) {
        long long key = (long long)g + threadIdx.x;
        int lo = 0, hi = NN;
        while (lo < hi) {
            int m = (lo + hi) >> 1;
            if (ld_idx(batch, m) < key) lo = m + 1; else hi = m;
        }
        sb[threadIdx.x] = lo;
    }
    __syncthreads();
    int beg = sb[0], end = sb[1];
    int c = threadIdx.x;  // 64 cols
    float sum = 0.f;
    for (int r = beg; r < end; r++) sum += fmaxf(g_agg2[r * 64 + c], 0.f);
    float cnt = (float)(end - beg);
    out[g * 64 + c] = sum / fmaxf(cnt, 1.0f);
}

// ---------------- fork/join resources (static init: before mem checkpoints)
static cudaStream_t g_sB = []() {
    cudaStream_t s = nullptr;
    cudaStreamCreateWithFlags(&s, cudaStreamNonBlocking);
    return s;
}();
static cudaEvent_t g_eFork = []() {
    cudaEvent_t e = nullptr;
    cudaEventCreateWithFlags(&e, cudaEventDisableTiming);
    return e;
}();
static cudaEvent_t g_eJoin = []() {
    cudaEvent_t e = nullptr;
    cudaEventCreateWithFlags(&e, cudaEventDisableTiming);
    return e;
}();

// ---------------- driver ---------------------------------------------------
extern "C" void kernel_launch(void* const* d_in, const int* in_sizes, int n_in,
                              void* d_out, int out_size) {
    const float* x  = (const float*)d_in[0];
    const void*  ei = d_in[1];
    const void*  bt = d_in[2];
    const float* W1 = (const float*)d_in[3];
    const float* b1 = (const float*)d_in[4];
    const float* W2 = (const float*)d_in[5];
    const float* b2 = (const float*)d_in[6];
    float* out = (float*)d_out;

    const int SMEM1 = 2 * IND * 64 * (int)sizeof(float);  // 65536
    const int SMEM2 = 2 * HD * 64 * (int)sizeof(float);   // 32768
    cudaFuncSetAttribute(gemm1_kernel, cudaFuncAttributeMaxDynamicSharedMemorySize, SMEM1);
    cudaFuncSetAttribute(gemm2_kernel, cudaFuncAttributeMaxDynamicSharedMemorySize, SMEM2);

    bool fork = (g_sB != nullptr) && (g_eFork != nullptr) && (g_eJoin != nullptr);

    if (fork) {
        // side branch: gemm1 (independent of the CSR build) runs in parallel
        cudaEventRecord(g_eFork, 0);
        cudaStreamWaitEvent(g_sB, g_eFork, 0);
        gemm1_kernel<<<(NN + 63) / 64, 256, SMEM1, g_sB>>>(x, W1, b1);
        cudaEventRecord(g_eJoin, g_sB);
    }

    // main branch: CSR build
    init_kernel<<<(NN + 255) / 256, 256>>>(ei);
    count_kernel<<<(NE + 255) / 256, 256>>>(ei);
    scanA_kernel<<<SCAN_BLK, 1024>>>();
    scanB_kernel<<<1, 64>>>();
    fill_kernel<<<(NE + 255) / 256, 256>>>();

    if (fork) {
        cudaStreamWaitEvent(0, g_eJoin, 0);
    } else {
        gemm1_kernel<<<(NN + 63) / 64, 256, SMEM1>>>(x, W1, b1);
    }

    gather1_kernel<<<(NN * 16 + 255) / 256, 256>>>();
    gemm2_kernel<<<(NN + 63) / 64, 256, SMEM2>>>(W2, b2);
    gather2_kernel<<<(NN * 16 + 255) / 256, 256>>>();
    pool_kernel<<<NG, 64>>>(bt, out);
}

// round 10
// speedup vs baseline: 1.6203x; 1.3108x over previous
#include <cuda_runtime.h>

#define NN 50000
#define NE 800000
#define IND 128
#define HD 64
#define OD 64
#define NG 512

static const int SCAN_BLK = (NN + 1023) / 1024;  // 49

// ---------------- scratch (__device__ globals: no allocs allowed) ----------
__device__ int   g_is64;
__device__ int   g_degcnt[NN];
__device__ int   g_cursor[NN];
__device__ int   g_offsets[NN + 1];   // intra-block exclusive prefix; [NN]=NE absolute
__device__ int   g_blocksums[64];
__device__ int   g_blockbase[64];     // exclusive prefix of block sums
__device__ float g_dinv[NN];
__device__ int2  g_ed32[NE];          // packed (src,dst) int32, sequential
__device__ int2  g_edge[NE];          // (src, norm-bits) CSR by dst
__device__ float g_t1[NN * HD];
__device__ float g_agg1[NN * HD];
__device__ float g_t2[NN * OD];
__device__ float g_agg2[NN * OD];

// ---------------- helpers --------------------------------------------------
typedef unsigned long long ull;

__device__ __forceinline__ long long ld_idx(const void* p, long long i) {
    if (g_is64) return ((const long long*)p)[i];
    return (long long)((const int*)p)[i];
}

// final CSR offset (folds the per-block scan base in at read time)
__device__ __forceinline__ int off(int i) {
    int v = g_offsets[i];
    if (i < NN) v += g_blockbase[i >> 10];
    return v;
}

__device__ __forceinline__ ull pack2(float x, float y) {
    ull r; asm("mov.b64 %0, {%1, %2};" : "=l"(r) : "f"(x), "f"(y)); return r;
}
__device__ __forceinline__ float2 unpack2(ull v) {
    float2 f; asm("mov.b64 {%0, %1}, %2;" : "=f"(f.x), "=f"(f.y) : "l"(v)); return f;
}
// d = a * b + d  (two independent fp32 FMAs, bit-identical to scalar fmaf)
__device__ __forceinline__ void ffma2(ull& d, ull a, ull b) {
    asm("fma.rn.f32x2 %0, %1, %2, %0;" : "+l"(d) : "l"(a), "l"(b));
}

// ---------------- init: zero counters + int64/int32 detect -----------------
__global__ void init_kernel(const void* __restrict__ ei) {
    int i = blockIdx.x * blockDim.x + threadIdx.x;
    if (i < NN) { g_degcnt[i] = 0; g_cursor[i] = 0; }
    if (i == 0) {
        const long long* p = (const long long*)ei;
        int ok = 1;
        for (int j = 0; j < 64; j++) {
            long long v = p[j];
            if (v < 0 || v >= NN) { ok = 0; break; }
        }
        g_is64 = ok;  // int32 data read as int64 fails the range check w.h.p.
    }
}

// count + decode int64 -> packed int32 pairs (fill re-reads the cheap form)
__global__ void count_kernel(const void* __restrict__ ei) {
    int e = blockIdx.x * blockDim.x + threadIdx.x;
    if (e < NE) {
        int s = (int)ld_idx(ei, e);
        int d = (int)ld_idx(ei, (long long)NE + e);
        g_ed32[e] = make_int2(s, d);
        atomicAdd(&g_degcnt[d], 1);
    }
}

// per-block (1024) exclusive scan of degcnt; also emits dinv + block sums
__global__ void __launch_bounds__(1024) scanA_kernel() {
    __shared__ int s[1024];
    int t = threadIdx.x;
    int idx = blockIdx.x * 1024 + t;
    int v = (idx < NN) ? g_degcnt[idx] : 0;
    s[t] = v;
    __syncthreads();
    for (int o = 1; o < 1024; o <<= 1) {
        int tmp = (t >= o) ? s[t - o] : 0;
        __syncthreads();
        if (t >= o) s[t] += tmp;
        __syncthreads();
    }
    if (idx < NN) {
        g_offsets[idx] = s[t] - v;  // exclusive within block
        g_dinv[idx] = rsqrtf(fmaxf((float)v, 1.0f));
    }
    if (t == 1023) g_blocksums[blockIdx.x] = s[1023];
}

// tiny scan of the 49 block sums
__global__ void scanB_kernel() {
    __shared__ int s[64];
    int t = threadIdx.x;
    int v = (t < SCAN_BLK) ? g_blocksums[t] : 0;
    s[t] = v;
    __syncthreads();
    for (int o = 1; o < 64; o <<= 1) {
        int tmp = (t >= o) ? s[t - o] : 0;
        __syncthreads();
        if (t >= o) s[t] += tmp;
        __syncthreads();
    }
    g_blockbase[t] = s[t] - v;  // exclusive
    if (t == 0) g_offsets[NN] = NE;
}

__global__ void fill_kernel() {
    int e = blockIdx.x * blockDim.x + threadIdx.x;
    if (e < NE) {
        int2 sd = g_ed32[e];
        int pos = off(sd.y) + atomicAdd(&g_cursor[sd.y], 1);
        g_edge[pos] = make_int2(sd.x, __float_as_int(g_dinv[sd.x] * g_dinv[sd.y]));
    }
}

// ---------------- dense GEMM: 64 rows x 64 cols per block, FFMA2 mainloop --
template <int K, bool RELU>
__device__ __forceinline__ void gemm_body(const float* __restrict__ A,
                                          const float* __restrict__ W,
                                          const float* __restrict__ bias,
                                          float* __restrict__ out) {
    extern __shared__ float smem[];
    float* Ws = smem;           // K * 64
    float* As = smem + K * 64;  // K * 64
    const int t = threadIdx.x;
    const int rowbase = blockIdx.x * 64;
    constexpr int NQ = K / 4;

    {
        const float4* W4 = (const float4*)W;
        float4* Ws4 = (float4*)Ws;
        for (int i = t; i < K * 16; i += 256) Ws4[i] = W4[i];
    }
    for (int i = t; i < 64 * NQ; i += 256) {
        int r = i / NQ, kq = i - r * NQ;
        int row = rowbase + r;
        float4 v = make_float4(0.f, 0.f, 0.f, 0.f);
        if (row < NN) {
            v = ((const float4*)A)[row * NQ + kq];
            if (RELU) {
                v.x = fmaxf(v.x, 0.f); v.y = fmaxf(v.y, 0.f);
                v.z = fmaxf(v.z, 0.f); v.w = fmaxf(v.w, 0.f);
            }
        }
        int k0 = kq * 4;
        int rs = r ^ (k0 & 28);
        As[(k0 + 0) * 64 + rs] = v.x;
        As[(k0 + 1) * 64 + rs] = v.y;
        As[(k0 + 2) * 64 + rs] = v.z;
        As[(k0 + 3) * 64 + rs] = v.w;
    }
    __syncthreads();

    const int tx = t & 15, ty = t >> 4;
    const int c0 = tx * 4;
    const int r0 = ty * 4;

    ull ac[4][2];
#pragma unroll
    for (int j = 0; j < 4; j++) { ac[j][0] = 0ULL; ac[j][1] = 0ULL; }

#pragma unroll 8
    for (int k = 0; k < K; k++) {
        const float* wrow = Ws + k * 64 + c0;
        ull b01 = *(const ull*)(wrow);
        ull b23 = *(const ull*)(wrow + 2);
        float4 xv = *(const float4*)(As + k * 64 + (r0 ^ (k & 28)));
        ull x0 = pack2(xv.x, xv.x);
        ull x1 = pack2(xv.y, xv.y);
        ull x2 = pack2(xv.z, xv.z);
        ull x3 = pack2(xv.w, xv.w);
        ffma2(ac[0][0], x0, b01); ffma2(ac[0][1], x0, b23);
        ffma2(ac[1][0], x1, b01); ffma2(ac[1][1], x1, b23);
        ffma2(ac[2][0], x2, b01); ffma2(ac[2][1], x2, b23);
        ffma2(ac[3][0], x3, b01); ffma2(ac[3][1], x3, b23);
    }

    float4 bb = *(const float4*)(bias + c0);
#pragma unroll
    for (int j = 0; j < 4; j++) {
        int row = rowbase + r0 + j;
        if (row < NN) {
            float2 p01 = unpack2(ac[j][0]);
            float2 p23 = unpack2(ac[j][1]);
            *(float4*)&out[row * 64 + c0] =
                make_float4(p01.x + bb.x, p01.y + bb.y, p23.x + bb.z, p23.y + bb.w);
        }
    }
}

__global__ void __launch_bounds__(256) gemm1_kernel(const float* __restrict__ x,
                                                    const float* __restrict__ W,
                                                    const float* __restrict__ b) {
    gemm_body<IND, false>(x, W, b, g_t1);
}
__global__ void __launch_bounds__(256) gemm2_kernel(const float* __restrict__ W,
                                                    const float* __restrict__ b) {
    gemm_body<HD, true>(g_agg1, W, b, g_t2);
}

// ---------------- CSR gather aggregation: 16 lanes (float4) per node -------
__device__ __forceinline__ void gather_body(const float* __restrict__ feat,
                                            float* __restrict__ out) {
    int tid = blockIdx.x * blockDim.x + threadIdx.x;
    int node = tid >> 4;
    int lane = tid & 15;
    if (node >= NN) return;
    int beg = off(node), end = off(node + 1);
    const float4* f4 = (const float4*)feat;
    float4 a0 = make_float4(0.f, 0.f, 0.f, 0.f);
    float4 a1 = make_float4(0.f, 0.f, 0.f, 0.f);
    int e = beg;
    for (; e + 2 <= end; e += 2) {
        int2 ed0 = g_edge[e];
        int2 ed1 = g_edge[e + 1];
        float4 v0 = f4[ed0.x * 16 + lane];
        float4 v1 = f4[ed1.x * 16 + lane];
        float w0 = __int_as_float(ed0.y);
        float w1 = __int_as_float(ed1.y);
        a0.x = fmaf(v0.x, w0, a0.x); a0.y = fmaf(v0.y, w0, a0.y);
        a0.z = fmaf(v0.z, w0, a0.z); a0.w = fmaf(v0.w, w0, a0.w);
        a1.x = fmaf(v1.x, w1, a1.x); a1.y = fmaf(v1.y, w1, a1.y);
        a1.z = fmaf(v1.z, w1, a1.z); a1.w = fmaf(v1.w, w1, a1.w);
    }
    if (e < end) {
        int2 ed = g_edge[e];
        float4 v = f4[ed.x * 16 + lane];
        float w = __int_as_float(ed.y);
        a0.x = fmaf(v.x, w, a0.x); a0.y = fmaf(v.y, w, a0.y);
        a0.z = fmaf(v.z, w, a0.z); a0.w = fmaf(v.w, w, a0.w);
    }
    ((float4*)out)[node * 16 + lane] =
        make_float4(a0.x + a1.x, a0.y + a1.y, a0.z + a1.z, a0.w + a1.w);
}

__global__ void __launch_bounds__(256) gather1_kernel() { gather_body(g_t1, g_agg1); }
__global__ void __launch_bounds__(256) gather2_kernel() { gather_body(g_t2, g_agg2); }

// ---------------- segment-mean pooling over sorted batch (relu fused) ------
__global__ void pool_kernel(const void* __restrict__ batch, float* __restrict__ out) {
    __shared__ int sb[2];
    int g = blockIdx.x;
    if (threadIdx.x < 2) {
        long long key = (long long)g + threadIdx.x;
        int lo = 0, hi = NN;
        while (lo < hi) {
            int m = (lo + hi) >> 1;
            if (ld_idx(batch, m) < key) lo = m + 1; else hi = m;
        }
        sb[threadIdx.x] = lo;
    }
    __syncthreads();
    int beg = sb[0], end = sb[1];
    int c = threadIdx.x;  // 64 cols
    float sum = 0.f;
    for (int r = beg; r < end; r++) sum += fmaxf(g_agg2[r * 64 + c], 0.f);
    float cnt = (float)(end - beg);
    out[g * 64 + c] = sum / fmaxf(cnt, 1.0f);
}

// ---------------- driver (serial, default stream — the proven structure) ---
extern "C" void kernel_launch(void* const* d_in, const int* in_sizes, int n_in,
                              void* d_out, int out_size) {
    const float* x  = (const float*)d_in[0];
    const void*  ei = d_in[1];
    const void*  bt = d_in[2];
    const float* W1 = (const float*)d_in[3];
    const float* b1 = (const float*)d_in[4];
    const float* W2 = (const float*)d_in[5];
    const float* b2 = (const float*)d_in[6];
    float* out = (float*)d_out;

    const int SMEM1 = 2 * IND * 64 * (int)sizeof(float);  // 65536
    const int SMEM2 = 2 * HD * 64 * (int)sizeof(float);   // 32768
    cudaFuncSetAttribute(gemm1_kernel, cudaFuncAttributeMaxDynamicSharedMemorySize, SMEM1);
    cudaFuncSetAttribute(gemm2_kernel, cudaFuncAttributeMaxDynamicSharedMemorySize, SMEM2);

    init_kernel<<<(NN + 255) / 256, 256>>>(ei);
    count_kernel<<<(NE + 255) / 256, 256>>>(ei);
    scanA_kernel<<<SCAN_BLK, 1024>>>();
    scanB_kernel<<<1, 64>>>();
    fill_kernel<<<(NE + 255) / 256, 256>>>();

    gemm1_kernel<<<(NN + 63) / 64, 256, SMEM1>>>(x, W1, b1);
    gather1_kernel<<<(NN * 16 + 255) / 256, 256>>>();
    gemm2_kernel<<<(NN + 63) / 64, 256, SMEM2>>>(W2, b2);
    gather2_kernel<<<(NN * 16 + 255) / 256, 256>>>();
    pool_kernel<<<NG, 64>>>(bt, out);
}

// round 12
// speedup vs baseline: 1.7026x; 1.0508x over previous
#include <cuda_runtime.h>
#include <cuda_fp16.h>

#define NN 50000
#define NE 800000
#define IND 128
#define HD 64
#define OD 64
#define NG 512

static const int SCAN_BLK = (NN + 1023) / 1024;  // 49

// ---------------- scratch (__device__ globals: no allocs allowed) ----------
__device__ int   g_is64;              // written by count block 0 (for pool)
__device__ int   g_degcnt[NN];        // zero at load; scanA re-zeroes each run
__device__ int   g_cursor[NN];        // zero at load; scanA re-zeroes each run
__device__ int   g_offsets[NN + 1];   // intra-block exclusive prefix; [NN]=NE absolute
__device__ int   g_blocksums[64];
__device__ int   g_blockbase[64];     // exclusive prefix of block sums
__device__ float g_dinv[NN];
__device__ int2  g_ed32[NE];          // packed (src,dst) int32, sequential
__device__ int2  g_edge[NE];          // (src, norm-bits) CSR by dst
__device__ uint2 g_t1h[NN * 16];      // fp16 features, 64 halves/row
__device__ float g_agg1[NN * HD];
__device__ uint2 g_t2h[NN * 16];      // fp16 features, 64 halves/row
__device__ float g_agg2[NN * OD];

// ---------------- helpers --------------------------------------------------
typedef unsigned long long ull;

// final CSR offset (folds the per-block scan base in at read time)
__device__ __forceinline__ int off(int i) {
    int v = g_offsets[i];
    if (i < NN) v += g_blockbase[i >> 10];
    return v;
}

__device__ __forceinline__ ull pack2(float x, float y) {
    ull r; asm("mov.b64 %0, {%1, %2};" : "=l"(r) : "f"(x), "f"(y)); return r;
}
__device__ __forceinline__ float2 unpack2(ull v) {
    float2 f; asm("mov.b64 {%0, %1}, %2;" : "=f"(f.x), "=f"(f.y) : "l"(v)); return f;
}
// d = a * b + d  (two independent fp32 FMAs, bit-identical to scalar fmaf)
__device__ __forceinline__ void ffma2(ull& d, ull a, ull b) {
    asm("fma.rn.f32x2 %0, %1, %2, %0;" : "+l"(d) : "l"(a), "l"(b));
}

// 8-sample int64-vs-int32 classifier on values expected in [0, lim).
// int32 data read as int64 pairs two values; high word != 0 w.h.p.
__device__ __forceinline__ int detect64(const void* p, long long lim) {
    const long long* q = (const long long*)p;
    int ok = 1;
#pragma unroll
    for (int j = 0; j < 8; j++) {
        long long v = q[j * 37 + 1];
        if (v < 0 || v >= lim) ok = 0;
    }
    return ok;
}

// ---------------- count: detect + decode + degree histogram ----------------
__global__ void count_kernel(const void* __restrict__ ei) {
    __shared__ int s64;
    if (threadIdx.x == 0) {
        int ok = detect64(ei, NN);   // samples src values (uniform, never leading-zero)
        s64 = ok;
        if (blockIdx.x == 0) g_is64 = ok;  // published for pool (later launch)
    }
    __syncthreads();
    int is64 = s64;
    int e = blockIdx.x * blockDim.x + threadIdx.x;
    if (e < NE) {
        int s, d;
        if (is64) {
            s = (int)((const long long*)ei)[e];
            d = (int)((const long long*)ei)[(long long)NE + e];
        } else {
            s = ((const int*)ei)[e];
            d = ((const int*)ei)[NE + e];
        }
        g_ed32[e] = make_int2(s, d);
        atomicAdd(&g_degcnt[d], 1);
    }
}

// per-block (1024) exclusive scan of degcnt; emits dinv + block sums.
// Also restores degcnt/cursor to zero for the next graph replay.
__global__ void __launch_bounds__(1024) scanA_kernel() {
    __shared__ int s[1024];
    int t = threadIdx.x;
    int idx = blockIdx.x * 1024 + t;
    int v = (idx < NN) ? g_degcnt[idx] : 0;
    s[t] = v;
    __syncthreads();
    for (int o = 1; o < 1024; o <<= 1) {
        int tmp = (t >= o) ? s[t - o] : 0;
        __syncthreads();
        if (t >= o) s[t] += tmp;
        __syncthreads();
    }
    if (idx < NN) {
        g_offsets[idx] = s[t] - v;  // exclusive within block
        g_dinv[idx] = rsqrtf(fmaxf((float)v, 1.0f));
        g_degcnt[idx] = 0;          // reset for next run
        g_cursor[idx] = 0;          // reset before fill (this run) & next run
    }
    if (t == 1023) g_blocksums[blockIdx.x] = s[1023];
}

// tiny scan of the 49 block sums
__global__ void scanB_kernel() {
    __shared__ int s[64];
    int t = threadIdx.x;
    int v = (t < SCAN_BLK) ? g_blocksums[t] : 0;
    s[t] = v;
    __syncthreads();
    for (int o = 1; o < 64; o <<= 1) {
        int tmp = (t >= o) ? s[t - o] : 0;
        __syncthreads();
        if (t >= o) s[t] += tmp;
        __syncthreads();
    }
    g_blockbase[t] = s[t] - v;  // exclusive
    if (t == 0) g_offsets[NN] = NE;
}

__global__ void fill_kernel() {
    int e = blockIdx.x * blockDim.x + threadIdx.x;
    if (e < NE) {
        int2 sd = g_ed32[e];
        int pos = off(sd.y) + atomicAdd(&g_cursor[sd.y], 1);
        g_edge[pos] = make_int2(sd.x, __float_as_int(g_dinv[sd.x] * g_dinv[sd.y]));
    }
}

// ---------------- dense GEMM: 64x64 tile, FFMA2 mainloop, fp16 output ------
template <int K, bool RELU>
__device__ __forceinline__ void gemm_body(const float* __restrict__ A,
                                          const float* __restrict__ W,
                                          const float* __restrict__ bias,
                                          uint2* __restrict__ outh) {
    extern __shared__ float smem[];
    float* Ws = smem;           // K * 64
    float* As = smem + K * 64;  // K * 64
    const int t = threadIdx.x;
    const int rowbase = blockIdx.x * 64;
    constexpr int NQ = K / 4;

    {
        const float4* W4 = (const float4*)W;
        float4* Ws4 = (float4*)Ws;
        for (int i = t; i < K * 16; i += 256) Ws4[i] = W4[i];
    }
    for (int i = t; i < 64 * NQ; i += 256) {
        int r = i / NQ, kq = i - r * NQ;
        int row = rowbase + r;
        float4 v = make_float4(0.f, 0.f, 0.f, 0.f);
        if (row < NN) {
            v = ((const float4*)A)[row * NQ + kq];
            if (RELU) {
                v.x = fmaxf(v.x, 0.f); v.y = fmaxf(v.y, 0.f);
                v.z = fmaxf(v.z, 0.f); v.w = fmaxf(v.w, 0.f);
            }
        }
        int k0 = kq * 4;
        int rs = r ^ (k0 & 28);
        As[(k0 + 0) * 64 + rs] = v.x;
        As[(k0 + 1) * 64 + rs] = v.y;
        As[(k0 + 2) * 64 + rs] = v.z;
        As[(k0 + 3) * 64 + rs] = v.w;
    }
    __syncthreads();

    const int tx = t & 15, ty = t >> 4;
    const int c0 = tx * 4;
    const int r0 = ty * 4;

    ull ac[4][2];
#pragma unroll
    for (int j = 0; j < 4; j++) { ac[j][0] = 0ULL; ac[j][1] = 0ULL; }

#pragma unroll 8
    for (int k = 0; k < K; k++) {
        const float* wrow = Ws + k * 64 + c0;
        ull b01 = *(const ull*)(wrow);
        ull b23 = *(const ull*)(wrow + 2);
        float4 xv = *(const float4*)(As + k * 64 + (r0 ^ (k & 28)));
        ull x0 = pack2(xv.x, xv.x);
        ull x1 = pack2(xv.y, xv.y);
        ull x2 = pack2(xv.z, xv.z);
        ull x3 = pack2(xv.w, xv.w);
        ffma2(ac[0][0], x0, b01); ffma2(ac[0][1], x0, b23);
        ffma2(ac[1][0], x1, b01); ffma2(ac[1][1], x1, b23);
        ffma2(ac[2][0], x2, b01); ffma2(ac[2][1], x2, b23);
        ffma2(ac[3][0], x3, b01); ffma2(ac[3][1], x3, b23);
    }

    float4 bb = *(const float4*)(bias + c0);
#pragma unroll
    for (int j = 0; j < 4; j++) {
        int row = rowbase + r0 + j;
        if (row < NN) {
            float2 p01 = unpack2(ac[j][0]);
            float2 p23 = unpack2(ac[j][1]);
            __half2 h01 = __floats2half2_rn(p01.x + bb.x, p01.y + bb.y);
            __half2 h23 = __floats2half2_rn(p23.x + bb.z, p23.y + bb.w);
            uint2 u;
            u.x = *(unsigned int*)&h01;
            u.y = *(unsigned int*)&h23;
            outh[row * 16 + tx] = u;  // cols [4tx, 4tx+4)
        }
    }
}

__global__ void __launch_bounds__(256) gemm1_kernel(const float* __restrict__ x,
                                                    const float* __restrict__ W,
                                                    const float* __restrict__ b) {
    gemm_body<IND, false>(x, W, b, g_t1h);
}
__global__ void __launch_bounds__(256) gemm2_kernel(const float* __restrict__ W,
                                                    const float* __restrict__ b) {
    gemm_body<HD, true>(g_agg1, W, b, g_t2h);
}

// ---------------- CSR gather: 16 lanes/node, fp16 in -> fp32 accum/out -----
__device__ __forceinline__ void gather_body(const uint2* __restrict__ feat,
                                            float* __restrict__ out) {
    int tid = blockIdx.x * blockDim.x + threadIdx.x;
    int node = tid >> 4;
    int lane = tid & 15;
    if (node >= NN) return;
    int beg = off(node), end = off(node + 1);
    float4 a0 = make_float4(0.f, 0.f, 0.f, 0.f);
    float4 a1 = make_float4(0.f, 0.f, 0.f, 0.f);
    int e = beg;
    for (; e + 2 <= end; e += 2) {
        int2 ed0 = g_edge[e];
        int2 ed1 = g_edge[e + 1];
        uint2 u0 = feat[ed0.x * 16 + lane];   // 128B coalesced row
        uint2 u1 = feat[ed1.x * 16 + lane];
        float w0 = __int_as_float(ed0.y);
        float w1 = __int_as_float(ed1.y);
        float2 l0 = __half22float2(*(__half2*)&u0.x);
        float2 h0 = __half22float2(*(__half2*)&u0.y);
        float2 l1 = __half22float2(*(__half2*)&u1.x);
        float2 h1 = __half22float2(*(__half2*)&u1.y);
        a0.x = fmaf(l0.x, w0, a0.x); a0.y = fmaf(l0.y, w0, a0.y);
        a0.z = fmaf(h0.x, w0, a0.z); a0.w = fmaf(h0.y, w0, a0.w);
        a1.x = fmaf(l1.x, w1, a1.x); a1.y = fmaf(l1.y, w1, a1.y);
        a1.z = fmaf(h1.x, w1, a1.z); a1.w = fmaf(h1.y, w1, a1.w);
    }
    if (e < end) {
        int2 ed = g_edge[e];
        uint2 u = feat[ed.x * 16 + lane];
        float w = __int_as_float(ed.y);
        float2 lo = __half22float2(*(__half2*)&u.x);
        float2 hi = __half22float2(*(__half2*)&u.y);
        a0.x = fmaf(lo.x, w, a0.x); a0.y = fmaf(lo.y, w, a0.y);
        a0.z = fmaf(hi.x, w, a0.z); a0.w = fmaf(hi.y, w, a0.w);
    }
    ((float4*)out)[node * 16 + lane] =
        make_float4(a0.x + a1.x, a0.y + a1.y, a0.z + a1.z, a0.w + a1.w);
}

__global__ void __launch_bounds__(256) gather1_kernel() { gather_body(g_t1h, g_agg1); }
__global__ void __launch_bounds__(256) gather2_kernel() { gather_body(g_t2h, g_agg2); }

// ---------------- segment-mean pooling over sorted batch (relu fused) ------
__global__ void pool_kernel(const void* __restrict__ batch, float* __restrict__ out) {
    __shared__ int sb[2];
    int g = blockIdx.x;
    int is64 = g_is64;
    if (threadIdx.x < 2) {
        long long key = (long long)g + threadIdx.x;
        int lo = 0, hi = NN;
        while (lo < hi) {
            int m = (lo + hi) >> 1;
            long long v = is64 ? ((const long long*)batch)[m]
                               : (long long)((const int*)batch)[m];
            if (v < key) lo = m + 1; else hi = m;
        }
        sb[threadIdx.x] = lo;
    }
    __syncthreads();
    int beg = sb[0], end = sb[1];
    int c = threadIdx.x;  // 64 cols
    float sum = 0.f;
    for (int r = beg; r < end; r++) sum += fmaxf(g_agg2[r * 64 + c], 0.f);
    float cnt = (float)(end - beg);
    out[g * 64 + c] = sum / fmaxf(cnt, 1.0f);
}

// ---------------- driver (serial, default stream — the proven structure) ---
extern "C" void kernel_launch(void* const* d_in, const int* in_sizes, int n_in,
                              void* d_out, int out_size) {
    const float* x  = (const float*)d_in[0];
    const void*  ei = d_in[1];
    const void*  bt = d_in[2];
    const float* W1 = (const float*)d_in[3];
    const float* b1 = (const float*)d_in[4];
    const float* W2 = (const float*)d_in[5];
    const float* b2 = (const float*)d_in[6];
    float* out = (float*)d_out;

    const int SMEM1 = 2 * IND * 64 * (int)sizeof(float);  // 65536
    const int SMEM2 = 2 * HD * 64 * (int)sizeof(float);   // 32768
    cudaFuncSetAttribute(gemm1_kernel, cudaFuncAttributeMaxDynamicSharedMemorySize, SMEM1);
    cudaFuncSetAttribute(gemm2_kernel, cudaFuncAttributeMaxDynamicSharedMemorySize, SMEM2);

    count_kernel<<<(NE + 255) / 256, 256>>>(ei);
    scanA_kernel<<<SCAN_BLK, 1024>>>();
    scanB_kernel<<<1, 64>>>();
    fill_kernel<<<(NE + 255) / 256, 256>>>();

    gemm1_kernel<<<(NN + 63) / 64, 256, SMEM1>>>(x, W1, b1);
    gather1_kernel<<<(NN * 16 + 255) / 256, 256>>>();
    gemm2_kernel<<<(NN + 63) / 64, 256, SMEM2>>>(W2, b2);
    gather2_kernel<<<(NN * 16 + 255) / 256, 256>>>();
    pool_kernel<<<NG, 64>>>(bt, out);
}

// round 16
// speedup vs baseline: 1.8179x; 1.0677x over previous
#include <cuda_runtime.h>
#include <cuda_fp16.h>

#define NN 50000
#define NE 800000
#define IND 128
#define HD 64
#define OD 64
#define NG 512

static const int SCAN_BLK = (NN + 1023) / 1024;  // 49

// ---------------- scratch (__device__ globals: no allocs allowed) ----------
__device__ int   g_is64;              // written by count block 0 (for pool)
__device__ int   g_scanctr;           // last-block ticket (reset each run)
__device__ int   g_degcnt[NN];        // zero at load; scanAB re-zeroes each run
__device__ int   g_cursor[NN];        // zero at load; scanAB re-zeroes each run
__device__ int   g_offsets[NN + 1];   // intra-block exclusive prefix; [NN]=NE absolute
__device__ int   g_blocksums[64];
__device__ int   g_blockbase[64];     // exclusive prefix of block sums
__device__ float g_dinv[NN];
__device__ int2  g_ed32[NE];          // packed (src,dst) int32, sequential
__device__ int2  g_edge[NE];          // (src, norm-bits) CSR by dst
__device__ uint2 g_t1h[NN * 16];      // fp16 features, 64 halves/row
__device__ uint2 g_t2h[NN * 16];      // fp16 features, 64 halves/row
__device__ float g_agg2[NN * OD];

// ---------------- helpers --------------------------------------------------
typedef unsigned long long ull;

// final CSR offset (folds the per-block scan base in at read time)
__device__ __forceinline__ int off(int i) {
    int v = g_offsets[i];
    if (i < NN) v += g_blockbase[i >> 10];
    return v;
}

__device__ __forceinline__ ull pack2(float x, float y) {
    ull r; asm("mov.b64 %0, {%1, %2};" : "=l"(r) : "f"(x), "f"(y)); return r;
}
__device__ __forceinline__ float2 unpack2(ull v) {
    float2 f; asm("mov.b64 {%0, %1}, %2;" : "=f"(f.x), "=f"(f.y) : "l"(v)); return f;
}
// d = a * b + d  (two independent fp32 FMAs, bit-identical to scalar fmaf)
__device__ __forceinline__ void ffma2(ull& d, ull a, ull b) {
    asm("fma.rn.f32x2 %0, %1, %2, %0;" : "+l"(d) : "l"(a), "l"(b));
}

// 8-sample int64-vs-int32 classifier on values expected in [0, lim).
__device__ __forceinline__ int detect64(const void* p, long long lim) {
    const long long* q = (const long long*)p;
    int ok = 1;
#pragma unroll
    for (int j = 0; j < 8; j++) {
        long long v = q[j * 37 + 1];
        if (v < 0 || v >= lim) ok = 0;
    }
    return ok;
}

// ---------------- count: detect + decode + degree histogram ----------------
__global__ void count_kernel(const void* __restrict__ ei) {
    __shared__ int s64;
    if (threadIdx.x == 0) {
        int ok = detect64(ei, NN);   // samples src values (uniform, never leading-zero)
        s64 = ok;
        if (blockIdx.x == 0) g_is64 = ok;  // published for pool (later launch)
    }
    __syncthreads();
    int is64 = s64;
    int e = blockIdx.x * blockDim.x + threadIdx.x;
    if (e < NE) {
        int s, d;
        if (is64) {
            s = (int)((const long long*)ei)[e];
            d = (int)((const long long*)ei)[(long long)NE + e];
        } else {
            s = ((const int*)ei)[e];
            d = ((const int*)ei)[NE + e];
        }
        g_ed32[e] = make_int2(s, d);
        atomicAdd(&g_degcnt[d], 1);
    }
}

// combined scan: per-block scan of degcnt + last-block scan of block sums.
// Also emits dinv and restores degcnt/cursor to zero for the next replay.
__global__ void __launch_bounds__(1024) scanAB_kernel() {
    __shared__ int s[1024];
    __shared__ int slast;
    int t = threadIdx.x;
    int idx = blockIdx.x * 1024 + t;
    int v = (idx < NN) ? g_degcnt[idx] : 0;
    s[t] = v;
    __syncthreads();
    for (int o = 1; o < 1024; o <<= 1) {
        int tmp = (t >= o) ? s[t - o] : 0;
        __syncthreads();
        if (t >= o) s[t] += tmp;
        __syncthreads();
    }
    if (idx < NN) {
        g_offsets[idx] = s[t] - v;  // exclusive within block
        g_dinv[idx] = rsqrtf(fmaxf((float)v, 1.0f));
        g_degcnt[idx] = 0;          // reset for next run
        g_cursor[idx] = 0;          // reset before fill (this run) & next run
    }
    if (t == 1023) g_blocksums[blockIdx.x] = s[1023];

    // last-block-finish: scan the 49 block sums
    if (t == 0) {
        __threadfence();
        slast = (atomicAdd(&g_scanctr, 1) == gridDim.x - 1);
    }
    __syncthreads();
    if (slast) {
        int v2 = 0;
        if (t < 64) {
            v2 = (t < SCAN_BLK) ? g_blocksums[t] : 0;
            s[t] = v2;
        }
        __syncthreads();
        for (int o = 1; o < 64; o <<= 1) {
            int tmp = (t >= o && t < 64) ? s[t - o] : 0;
            __syncthreads();
            if (t >= o && t < 64) s[t] += tmp;
            __syncthreads();
        }
        if (t < 64) g_blockbase[t] = s[t] - v2;  // exclusive
        if (t == 0) { g_offsets[NN] = NE; g_scanctr = 0; }
    }
}

__global__ void fill_kernel() {
    int e = blockIdx.x * blockDim.x + threadIdx.x;
    if (e < NE) {
        int2 sd = g_ed32[e];
        int pos = off(sd.y) + atomicAdd(&g_cursor[sd.y], 1);
        g_edge[pos] = make_int2(sd.x, __float_as_int(g_dinv[sd.x] * g_dinv[sd.y]));
    }
}

// ---------------- gemm mainloop pieces (shared by gemm1 and layer2) --------
// As layout: As[k*64 + (r ^ (k & 28))], 4-aligned XOR swizzle.
__device__ __forceinline__ void gemm_mainloop_64(const float* __restrict__ Ws,
                                                 const float* __restrict__ As,
                                                 int K, int c0, int r0,
                                                 ull ac[4][2]) {
#pragma unroll
    for (int j = 0; j < 4; j++) { ac[j][0] = 0ULL; ac[j][1] = 0ULL; }
#pragma unroll 8
    for (int k = 0; k < K; k++) {
        const float* wrow = Ws + k * 64 + c0;
        ull b01 = *(const ull*)(wrow);
        ull b23 = *(const ull*)(wrow + 2);
        float4 xv = *(const float4*)(As + k * 64 + (r0 ^ (k & 28)));
        ull x0 = pack2(xv.x, xv.x);
        ull x1 = pack2(xv.y, xv.y);
        ull x2 = pack2(xv.z, xv.z);
        ull x3 = pack2(xv.w, xv.w);
        ffma2(ac[0][0], x0, b01); ffma2(ac[0][1], x0, b23);
        ffma2(ac[1][0], x1, b01); ffma2(ac[1][1], x1, b23);
        ffma2(ac[2][0], x2, b01); ffma2(ac[2][1], x2, b23);
        ffma2(ac[3][0], x3, b01); ffma2(ac[3][1], x3, b23);
    }
}

__device__ __forceinline__ void gemm_store_h(uint2* __restrict__ outh,
                                             const float* __restrict__ bias,
                                             int rowbase, int r0, int c0, int tx,
                                             ull ac[4][2]) {
    float4 bb = *(const float4*)(bias + c0);
#pragma unroll
    for (int j = 0; j < 4; j++) {
        int row = rowbase + r0 + j;
        if (row < NN) {
            float2 p01 = unpack2(ac[j][0]);
            float2 p23 = unpack2(ac[j][1]);
            __half2 h01 = __floats2half2_rn(p01.x + bb.x, p01.y + bb.y);
            __half2 h23 = __floats2half2_rn(p23.x + bb.z, p23.y + bb.w);
            uint2 u;
            u.x = *(unsigned int*)&h01;
            u.y = *(unsigned int*)&h23;
            outh[row * 16 + tx] = u;  // cols [4tx, 4tx+4)
        }
    }
}

// ---------------- gemm1: x[NN,128] @ W1 + b1 -> fp16 g_t1h -----------------
__global__ void __launch_bounds__(256) gemm1_kernel(const float* __restrict__ A,
                                                    const float* __restrict__ W,
                                                    const float* __restrict__ bias) {
    extern __shared__ float smem[];
    float* Ws = smem;             // 128 * 64
    float* As = smem + IND * 64;  // 128 * 64
    const int t = threadIdx.x;
    const int rowbase = blockIdx.x * 64;
    constexpr int NQ = IND / 4;

    {
        const float4* W4 = (const float4*)W;
        float4* Ws4 = (float4*)Ws;
        for (int i = t; i < IND * 16; i += 256) Ws4[i] = W4[i];
    }
    for (int i = t; i < 64 * NQ; i += 256) {
        int r = i / NQ, kq = i - r * NQ;
        int row = rowbase + r;
        float4 v = make_float4(0.f, 0.f, 0.f, 0.f);
        if (row < NN) v = ((const float4*)A)[row * NQ + kq];
        int k0 = kq * 4;
        int rs = r ^ (k0 & 28);
        As[(k0 + 0) * 64 + rs] = v.x;
        As[(k0 + 1) * 64 + rs] = v.y;
        As[(k0 + 2) * 64 + rs] = v.z;
        As[(k0 + 3) * 64 + rs] = v.w;
    }
    __syncthreads();

    const int tx = t & 15, ty = t >> 4;
    ull ac[4][2];
    gemm_mainloop_64(Ws, As, IND, tx * 4, ty * 4, ac);
    gemm_store_h(g_t1h, bias, rowbase, ty * 4, tx * 4, tx, ac);
}

// ---------------- fused layer2: gather(g_t1h) + relu + @W2 + b2 -> g_t2h ---
__global__ void __launch_bounds__(256) layer2_kernel(const float* __restrict__ W,
                                                     const float* __restrict__ bias) {
    extern __shared__ float smem[];
    float* Ws = smem;            // 64 * 64
    float* As = smem + HD * 64;  // 64 * 64
    const int t = threadIdx.x;
    const int rowbase = blockIdx.x * 64;

    {
        const float4* W4 = (const float4*)W;
        float4* Ws4 = (float4*)Ws;
        for (int i = t; i < HD * 16; i += 256) Ws4[i] = W4[i];
    }

    // gather phase: 16 groups x 16 lanes; each group handles 4 nodes
    const int grp = t >> 4, lane = t & 15;
    const int k0 = lane * 4;
    for (int rr = grp; rr < 64; rr += 16) {
        int node = rowbase + rr;
        float4 a0 = make_float4(0.f, 0.f, 0.f, 0.f);
        float4 a1 = make_float4(0.f, 0.f, 0.f, 0.f);
        if (node < NN) {
            int beg = off(node), end = off(node + 1);
            int e = beg;
            for (; e + 2 <= end; e += 2) {
                int2 ed0 = g_edge[e];
                int2 ed1 = g_edge[e + 1];
                uint2 u0 = g_t1h[ed0.x * 16 + lane];
                uint2 u1 = g_t1h[ed1.x * 16 + lane];
                float w0 = __int_as_float(ed0.y);
                float w1 = __int_as_float(ed1.y);
                float2 l0 = __half22float2(*(__half2*)&u0.x);
                float2 h0 = __half22float2(*(__half2*)&u0.y);
                float2 l1 = __half22float2(*(__half2*)&u1.x);
                float2 h1 = __half22float2(*(__half2*)&u1.y);
                a0.x = fmaf(l0.x, w0, a0.x); a0.y = fmaf(l0.y, w0, a0.y);
                a0.z = fmaf(h0.x, w0, a0.z); a0.w = fmaf(h0.y, w0, a0.w);
                a1.x = fmaf(l1.x, w1, a1.x); a1.y = fmaf(l1.y, w1, a1.y);
                a1.z = fmaf(h1.x, w1, a1.z); a1.w = fmaf(h1.y, w1, a1.w);
            }
            if (e < end) {
                int2 ed = g_edge[e];
                uint2 u = g_t1h[ed.x * 16 + lane];
                float w = __int_as_float(ed.y);
                float2 lo = __half22float2(*(__half2*)&u.x);
                float2 hi = __half22float2(*(__half2*)&u.y);
                a0.x = fmaf(lo.x, w, a0.x); a0.y = fmaf(lo.y, w, a0.y);
                a0.z = fmaf(hi.x, w, a0.z); a0.w = fmaf(hi.y, w, a0.w);
            }
        }
        // relu(agg1) -> deposit into swizzled As (cols k0..k0+3, row rr)
        int rs = rr ^ (k0 & 28);
        As[(k0 + 0) * 64 + rs] = fmaxf(a0.x + a1.x, 0.f);
        As[(k0 + 1) * 64 + rs] = fmaxf(a0.y + a1.y, 0.f);
        As[(k0 + 2) * 64 + rs] = fmaxf(a0.z + a1.z, 0.f);
        As[(k0 + 3) * 64 + rs] = fmaxf(a0.w + a1.w, 0.f);
    }
    __syncthreads();

    const int tx = t & 15, ty = t >> 4;
    ull ac[4][2];
    gemm_mainloop_64(Ws, As, HD, tx * 4, ty * 4, ac);
    gemm_store_h(g_t2h, bias, rowbase, ty * 4, tx * 4, tx, ac);
}

// ---------------- CSR gather2: fp16 in -> fp32 accum/out -------------------
__global__ void __launch_bounds__(256) gather2_kernel() {
    int tid = blockIdx.x * blockDim.x + threadIdx.x;
    int node = tid >> 4;
    int lane = tid & 15;
    if (node >= NN) return;
    int beg = off(node), end = off(node + 1);
    float4 a0 = make_float4(0.f, 0.f, 0.f, 0.f);
    float4 a1 = make_float4(0.f, 0.f, 0.f, 0.f);
    int e = beg;
    for (; e + 2 <= end; e += 2) {
        int2 ed0 = g_edge[e];
        int2 ed1 = g_edge[e + 1];
        uint2 u0 = g_t2h[ed0.x * 16 + lane];
        uint2 u1 = g_t2h[ed1.x * 16 + lane];
        float w0 = __int_as_float(ed0.y);
        float w1 = __int_as_float(ed1.y);
        float2 l0 = __half22float2(*(__half2*)&u0.x);
        float2 h0 = __half22float2(*(__half2*)&u0.y);
        float2 l1 = __half22float2(*(__half2*)&u1.x);
        float2 h1 = __half22float2(*(__half2*)&u1.y);
        a0.x = fmaf(l0.x, w0, a0.x); a0.y = fmaf(l0.y, w0, a0.y);
        a0.z = fmaf(h0.x, w0, a0.z); a0.w = fmaf(h0.y, w0, a0.w);
        a1.x = fmaf(l1.x, w1, a1.x); a1.y = fmaf(l1.y, w1, a1.y);
        a1.z = fmaf(h1.x, w1, a1.z); a1.w = fmaf(h1.y, w1, a1.w);
    }
    if (e < end) {
        int2 ed = g_edge[e];
        uint2 u = g_t2h[ed.x * 16 + lane];
        float w = __int_as_float(ed.y);
        float2 lo = __half22float2(*(__half2*)&u.x);
        float2 hi = __half22float2(*(__half2*)&u.y);
        a0.x = fmaf(lo.x, w, a0.x); a0.y = fmaf(lo.y, w, a0.y);
        a0.z = fmaf(hi.x, w, a0.z); a0.w = fmaf(hi.y, w, a0.w);
    }
    ((float4*)g_agg2)[node * 16 + lane] =
        make_float4(a0.x + a1.x, a0.y + a1.y, a0.z + a1.z, a0.w + a1.w);
}

// ---------------- segment-mean pooling over sorted batch (relu fused) ------
__global__ void pool_kernel(const void* __restrict__ batch, float* __restrict__ out) {
    __shared__ int sb[2];
    int g = blockIdx.x;
    int is64 = g_is64;
    if (threadIdx.x < 2) {
        long long key = (long long)g + threadIdx.x;
        int lo = 0, hi = NN;
        while (lo < hi) {
            int m = (lo + hi) >> 1;
            long long v = is64 ? ((const long long*)batch)[m]
                               : (long long)((const int*)batch)[m];
            if (v < key) lo = m + 1; else hi = m;
        }
        sb[threadIdx.x] = lo;
    }
    __syncthreads();
    int beg = sb[0], end = sb[1];
    int c = threadIdx.x;  // 64 cols
    float sum = 0.f;
    for (int r = beg; r < end; r++) sum += fmaxf(g_agg2[r * 64 + c], 0.f);
    float cnt = (float)(end - beg);
    out[g * 64 + c] = sum / fmaxf(cnt, 1.0f);
}

// ---------------- driver (serial, default stream — the proven structure) ---
extern "C" void kernel_launch(void* const* d_in, const int* in_sizes, int n_in,
                              void* d_out, int out_size) {
    const float* x  = (const float*)d_in[0];
    const void*  ei = d_in[1];
    const void*  bt = d_in[2];
    const float* W1 = (const float*)d_in[3];
    const float* b1 = (const float*)d_in[4];
    const float* W2 = (const float*)d_in[5];
    const float* b2 = (const float*)d_in[6];
    float* out = (float*)d_out;

    const int SMEM1 = 2 * IND * 64 * (int)sizeof(float);  // 65536
    const int SMEM2 = 2 * HD * 64 * (int)sizeof(float);   // 32768
    cudaFuncSetAttribute(gemm1_kernel, cudaFuncAttributeMaxDynamicSharedMemorySize, SMEM1);
    cudaFuncSetAttribute(layer2_kernel, cudaFuncAttributeMaxDynamicSharedMemorySize, SMEM2);

    count_kernel<<<(NE + 255) / 256, 256>>>(ei);
    scanAB_kernel<<<SCAN_BLK, 1024>>>();
    fill_kernel<<<(NE + 255) / 256, 256>>>();

    gemm1_kernel<<<(NN + 63) / 64, 256, SMEM1>>>(x, W1, b1);
    layer2_kernel<<<(NN + 63) / 64, 256, SMEM2>>>(W2, b2);
    gather2_kernel<<<(NN * 16 + 255) / 256, 256>>>();
    pool_kernel<<<NG, 64>>>(bt, out);
}